// round 6
// baseline (speedup 1.0000x reference)
#include <cuda_runtime.h>

// Problem constants
#define BQ   32
#define TT   512
#define DDIM 512
#define HH   8
#define HD   64
#define TEDIM 2048
#define MROWS (BQ*TT)            // 16384
#define YN ((size_t)BQ*TT*DDIM)  // 8388608
#define SN ((size_t)BQ*HH*TT*TT) // 67108864
#define WSZ (DDIM*DDIM)          // 262144

// Scratch (device globals — no allocation allowed)
__device__ float g_xn[BQ*TT*DDIM];
__device__ float g_q [BQ*TT*DDIM];
__device__ float g_k [BQ*TT*DDIM];
__device__ float g_v [BQ*TT*DDIM];   // stored TRANSPOSED: [b][h*64+d][t]
__device__ float g_y [BQ*TT*DDIM];
__device__ float g_hs[BQ*TT*DDIM];
__device__ float g_sigma[BQ*HH*TT];
__device__ float g_style[BQ*2*DDIM];
__device__ float g_wr[4*WSZ];        // tf32-rounded [Wq;Wk;Wv] (1536x512) + outW

__device__ __forceinline__ float siluf(float z){ return z / (1.f + expf(-z)); }

__device__ __forceinline__ float tf32r(float f){
    unsigned u; asm("cvt.rna.tf32.f32 %0, %1;" : "=r"(u) : "f"(f));
    return __uint_as_float(u);
}

__device__ __forceinline__ void mma8(float* c,
    unsigned a0, unsigned a1, unsigned a2, unsigned a3,
    unsigned b0, unsigned b1)
{
    asm volatile(
        "mma.sync.aligned.m16n8k8.row.col.f32.tf32.tf32.f32 "
        "{%0,%1,%2,%3}, {%4,%5,%6,%7}, {%8,%9}, {%0,%1,%2,%3};"
        : "+f"(c[0]), "+f"(c[1]), "+f"(c[2]), "+f"(c[3])
        : "r"(a0), "r"(a1), "r"(a2), "r"(a3), "r"(b0), "r"(b1));
}

__device__ __forceinline__ void cp16(unsigned dst, const void* src){
    asm volatile("cp.async.cg.shared.global [%0], [%1], 16;" :: "r"(dst), "l"(src));
}
#define CPCOMMIT() asm volatile("cp.async.commit_group;" ::: "memory")
#define CPWAIT(n)  asm volatile("cp.async.wait_group %0;" :: "n"(n) : "memory")

__device__ __forceinline__ uint4 ldmx4(unsigned a){
    uint4 r;
    asm volatile("ldmatrix.sync.aligned.m8n8.x4.shared.b16 {%0,%1,%2,%3}, [%4];"
        : "=r"(r.x), "=r"(r.y), "=r"(r.z), "=r"(r.w) : "r"(a));
    return r;
}

// ---------------------------------------------------------------------------
// weight pre-round
// ---------------------------------------------------------------------------
__global__ void round_w_kernel(const float* __restrict__ w0, const float* __restrict__ w1,
                               const float* __restrict__ w2, const float* __restrict__ w3)
{
    int i = blockIdx.x * 256 + threadIdx.x;
    g_wr[i]         = tf32r(w0[i]);
    g_wr[i +   WSZ] = tf32r(w1[i]);
    g_wr[i + 2*WSZ] = tf32r(w2[i]);
    g_wr[i + 3*WSZ] = tf32r(w3[i]);
}

// ---------------------------------------------------------------------------
// LN1 + sigma (xn stored tf32-rounded)
// ---------------------------------------------------------------------------
__global__ void ln1_sigma_kernel(const float* __restrict__ x,
                                 const float* __restrict__ g,
                                 const float* __restrict__ b,
                                 const float* __restrict__ Wsig)
{
    int row = blockIdx.x;
    int tid = threadIdx.x;
    int warp = tid >> 5, lane = tid & 31;
    const float* xr = x + (size_t)row * DDIM;
    float x0 = xr[tid], x1 = xr[tid + 256];
    float s = x0 + x1, sq = x0*x0 + x1*x1;
    #pragma unroll
    for (int o = 16; o > 0; o >>= 1) {
        s  += __shfl_xor_sync(~0u, s,  o);
        sq += __shfl_xor_sync(~0u, sq, o);
    }
    __shared__ float sm[8], sm2[8];
    if (lane == 0) { sm[warp] = s; sm2[warp] = sq; }
    __syncthreads();
    float tot = 0.f, tot2 = 0.f;
    #pragma unroll
    for (int i = 0; i < 8; i++) { tot += sm[i]; tot2 += sm2[i]; }
    float mean = tot * (1.f / DDIM);
    float var  = tot2 * (1.f / DDIM) - mean * mean;
    float rstd = rsqrtf(var + 1e-5f);
    g_xn[(size_t)row*DDIM + tid]       = tf32r((x0 - mean) * rstd * g[tid]       + b[tid]);
    g_xn[(size_t)row*DDIM + tid + 256] = tf32r((x1 - mean) * rstd * g[tid + 256] + b[tid + 256]);

    float acc[HH];
    #pragma unroll
    for (int h = 0; h < HH; h++)
        acc[h] = x0 * Wsig[tid*HH + h] + x1 * Wsig[(tid+256)*HH + h];
    #pragma unroll
    for (int h = 0; h < HH; h++)
        #pragma unroll
        for (int o = 16; o > 0; o >>= 1)
            acc[h] += __shfl_xor_sync(~0u, acc[h], o);
    __shared__ float red[8][HH];
    if (lane == 0)
        #pragma unroll
        for (int h = 0; h < HH; h++) red[warp][h] = acc[h];
    __syncthreads();
    if (tid < HH) {
        float z = 0.f;
        #pragma unroll
        for (int w = 0; w < 8; w++) z += red[w][tid];
        float sg  = 1.f / (1.f + expf(-5.f * z)) + 1e-5f;
        float sig = exp2f(sg * 1.5849625007211562f) - 1.f;   // 3^sg - 1
        int bb = row / TT, t = row % TT;
        g_sigma[(bb*HH + tid)*TT + t] = sig;
    }
}

// ---------------------------------------------------------------------------
// tf32 NT GEMM v2 (BK=32, 3-stage cp.async, merged-QKV routing / outproj).
// ---------------------------------------------------------------------------
template<bool QKV>
__global__ void __launch_bounds__(256,2)
tf32_gemm2(const float* __restrict__ A, const float* __restrict__ Bw,
           float* __restrict__ Cq, float* __restrict__ Ck, float* __restrict__ Cv,
           const float* __restrict__ bias, const float* __restrict__ res)
{
    constexpr int ST  = 36;                // 32 + 4 pad (floats)
    constexpr int STG = 128*ST*4;          // per-operand stage bytes

    extern __shared__ float dsm[];
    const unsigned sb = (unsigned)__cvta_generic_to_shared(dsm);
    const unsigned aS = sb;
    const unsigned bS = sb + 3*STG;

    const int tid  = threadIdx.x;
    const int lane = tid & 31;
    const int wid  = tid >> 5;
    const int wm   = wid & 1;
    const int wn   = wid >> 1;
    const int g    = lane >> 2;
    const int t    = lane & 3;

    const int m0 = blockIdx.y * 128;
    const int n0 = blockIdx.x * 128;

    const int rl = tid >> 3;               // 0..31
    const int qc = tid & 7;                // 16B chunk in BK32

    const float* Ag = A  + (long)(m0 + rl) * 512 + qc*4;
    const float* Bg = Bw + (long)(n0 + rl) * 512 + qc*4;
    const unsigned dA = (unsigned)(rl*ST + qc*4) * 4;

    auto issue = [&](int st, int k0){
        unsigned ab = aS + st*STG, bb = bS + st*STG;
        #pragma unroll
        for (int e = 0; e < 4; e++){
            cp16(ab + dA + e*32*ST*4, Ag + (long)e*32*512 + k0);
            cp16(bb + dA + e*32*ST*4, Bg + (long)e*32*512 + k0);
        }
    };

    const int arow = (lane & 7) + ((lane >> 3) & 1) * 8;
    const int acol = (lane >> 4) * 4;
    const unsigned aFB = (unsigned)((wm*64 + arow)*ST + acol) * 4;
    const unsigned bFB = (unsigned)((wn*32 + (lane & 7))*ST + (lane >> 3)*4) * 4;

    float acc[4][4][4];
    #pragma unroll
    for (int i = 0; i < 4; i++)
        #pragma unroll
        for (int j = 0; j < 4; j++)
            #pragma unroll
            for (int p = 0; p < 4; p++) acc[i][j][p] = 0.f;

    issue(0, 0);  CPCOMMIT();
    issue(1, 32); CPCOMMIT();

    int buf = 0;
    for (int k0 = 0; k0 < 512; k0 += 32) {
        CPWAIT(1);
        __syncthreads();
        if (k0 + 64 < 512) {
            int nb = buf + 2; if (nb >= 3) nb -= 3;
            issue(nb, k0 + 64);
        }
        CPCOMMIT();

        const unsigned ab = aS + buf*STG;
        const unsigned bb = bS + buf*STG;

        uint4 bfr[4][2];
        #pragma unroll
        for (int nt = 0; nt < 4; nt++)
            #pragma unroll
            for (int kg = 0; kg < 2; kg++)
                bfr[nt][kg] = ldmx4(bb + bFB + (unsigned)(nt*8*ST + kg*16)*4);

        #pragma unroll
        for (int ks = 0; ks < 4; ks++) {
            #pragma unroll
            for (int mt = 0; mt < 4; mt++) {
                uint4 a = ldmx4(ab + aFB + (unsigned)(mt*16*ST + ks*8)*4);
                #pragma unroll
                for (int nt = 0; nt < 4; nt++)
                    mma8(acc[mt][nt], a.x, a.y, a.z, a.w,
                         (ks & 1) ? bfr[nt][ks>>1].z : bfr[nt][ks>>1].x,
                         (ks & 1) ? bfr[nt][ks>>1].w : bfr[nt][ks>>1].y);
            }
        }
        buf++; if (buf == 3) buf = 0;
    }

    // Epilogue
    #pragma unroll
    for (int mt = 0; mt < 4; mt++){
        #pragma unroll
        for (int nt = 0; nt < 4; nt++){
            int row = m0 + wm*64 + mt*16 + g;
            int col = n0 + wn*32 + nt*8 + 2*t;
            float v0 = acc[mt][nt][0], v1 = acc[mt][nt][1];
            float v2 = acc[mt][nt][2], v3 = acc[mt][nt][3];
            if (QKV){
                v0 = tf32r(v0); v1 = tf32r(v1); v2 = tf32r(v2); v3 = tf32r(v3);
                if (n0 < 512){
                    *(float2*)&Cq[(long)row*512 + col]     = make_float2(v0, v1);
                    *(float2*)&Cq[(long)(row+8)*512 + col] = make_float2(v2, v3);
                } else if (n0 < 1024){
                    int c2 = col - 512;
                    *(float2*)&Ck[(long)row*512 + c2]     = make_float2(v0, v1);
                    *(float2*)&Ck[(long)(row+8)*512 + c2] = make_float2(v2, v3);
                } else {
                    int vc = col - 1024;
                    long base0 = (long)(row >> 9) * (512L*512) + (row & 511);
                    Cv[base0 + (long)vc*512]         = v0;
                    Cv[base0 + (long)(vc+1)*512]     = v1;
                    Cv[base0 + 8 + (long)vc*512]     = v2;
                    Cv[base0 + 8 + (long)(vc+1)*512] = v3;
                }
            } else {
                v0 += bias[col];   v1 += bias[col+1];
                v2 += bias[col];   v3 += bias[col+1];
                v0 += res[(long)row*512 + col];
                v1 += res[(long)row*512 + col+1];
                v2 += res[(long)(row+8)*512 + col];
                v3 += res[(long)(row+8)*512 + col+1];
                *(float2*)&Cq[(long)row*512 + col]     = make_float2(v0, v1);
                *(float2*)&Cq[(long)(row+8)*512 + col] = make_float2(v2, v3);
            }
        }
    }
}

// ---------------------------------------------------------------------------
// Fused scores + softmax + AV (flash-style).  FIXED issueV (full 64x128 tile).
// series[bh, m0:m0+32, :] written fp32; y[32,64] accumulated in-kernel.
// ---------------------------------------------------------------------------
__global__ void __launch_bounds__(256,2)
fused_attn_kernel(const float* __restrict__ Q, const float* __restrict__ Kt,
                  const float* __restrict__ Vt,
                  float* __restrict__ S, float* __restrict__ Y)
{
    constexpr int AST = 68;
    constexpr int BST = 68;
    constexpr int VST = 132;
    constexpr int SST = 132;
    const unsigned A_BYTES = 32*AST*4;            // 8704
    const unsigned B_BYTES = 128*BST*4;           // 34816

    extern __shared__ float dsm[];
    const unsigned sb  = (unsigned)__cvta_generic_to_shared(dsm);
    const unsigned sbA = sb;
    const unsigned sbB = sb + A_BYTES;
    const unsigned sbS = sb + A_BYTES + 2*B_BYTES;       // series chunk 32x132
    float* red = dsm + (A_BYTES + 2*B_BYTES)/4 + 32*SST; // [32][4]

    const int tid  = threadIdx.x;
    const int lane = tid & 31;
    const int wid  = tid >> 5;
    const int wm   = wid & 1;
    const int wn   = wid >> 1;        // 0..3
    const int g    = lane >> 2;
    const int t    = lane & 3;

    const int bh = blockIdx.y;        // b*8+h
    const int b  = bh >> 3, h = bh & 7;
    const int m0 = blockIdx.x * 32;

    const float* Qb = Q + ((long)b*512 + m0)*512 + h*64;
    const float* Kb = Kt + ((long)b*512)*512 + h*64;
    const float* Vb = Vt + (long)b*(512L*512) + (long)h*64*512; // [64 d][512 t]
    float* Sb = S + ((long)bh*512 + m0)*512;
    float* Yb = Y + ((long)b*512)*512 + h*64;

    const int arow = (lane & 7) + ((lane >> 3) & 1) * 8;
    const int acol = (lane >> 4) * 4;
    const unsigned aF  = sbA + (unsigned)((wm*16 + arow)*AST + acol) * 4;
    const unsigned bF  = (unsigned)((wn*32 + (lane & 7))*BST + (lane >> 3)*4) * 4;
    const unsigned sF  = sbS + (unsigned)((wm*16 + arow)*SST + acol) * 4;
    const unsigned vF  = (unsigned)((wn*16 + (lane & 7))*VST + (lane >> 3)*4) * 4;

    auto issueB = [&](int chunk, int bufb){
        unsigned dst = sbB + (unsigned)bufb * B_BYTES;
        const float* src = Kb + (long)(chunk*128)*512;
        #pragma unroll
        for (int e = 0; e < 8; e++){
            int idx = tid + 256*e;
            int r = idx >> 4, c4 = idx & 15;
            cp16(dst + (unsigned)(r*BST + c4*4)*4, src + (long)r*512 + c4*4);
        }
    };
    // FIXED: full 64 rows x 128 cols = 2048 cp16 (was 512 -> read garbage)
    auto issueV = [&](int chunk, int bufb){
        unsigned dst = sbB + (unsigned)bufb * B_BYTES;
        #pragma unroll
        for (int e = 0; e < 8; e++){
            int idx = tid + 256*e;        // 0..2047
            int r  = idx >> 5;            // 0..63  (d-row)
            int qc = idx & 31;            // 0..31  (16B chunk of 128 t-cols)
            cp16(dst + (unsigned)(r*VST + qc*4)*4,
                 Vb + (long)r*512 + chunk*128 + qc*4);
        }
    };

    // group 0: Q tile + K chunk 0
    {
        #pragma unroll
        for (int e = 0; e < 2; e++){
            int idx = tid + 256*e;
            int r = idx >> 4, c4 = idx & 15;
            cp16(sbA + (unsigned)(r*AST + c4*4)*4, Qb + (long)r*512 + c4*4);
        }
        issueB(0, 0);
        CPCOMMIT();
    }

    float acc[4][4][4];
    #pragma unroll
    for (int c = 0; c < 4; c++)
        #pragma unroll
        for (int nt = 0; nt < 4; nt++)
            #pragma unroll
            for (int p = 0; p < 4; p++) acc[c][nt][p] = 0.f;

    for (int c = 0; c < 4; c++){
        CPWAIT(0);
        __syncthreads();
        if (c + 1 < 4) issueB(c + 1, (c + 1) & 1);
        CPCOMMIT();

        const unsigned bb = sbB + (unsigned)(c & 1) * B_BYTES;
        #pragma unroll
        for (int kg = 0; kg < 4; kg++){
            uint4 a0 = ldmx4(aF + (unsigned)(kg*16 + 0)*4);
            uint4 a1 = ldmx4(aF + (unsigned)(kg*16 + 8)*4);
            #pragma unroll
            for (int nt = 0; nt < 4; nt++){
                uint4 bv = ldmx4(bb + bF + (unsigned)(nt*8*BST + kg*16)*4);
                mma8(acc[c][nt], a0.x, a0.y, a0.z, a0.w, bv.x, bv.y);
                mma8(acc[c][nt], a1.x, a1.y, a1.z, a1.w, bv.z, bv.w);
            }
        }
        __syncthreads();
    }

    // prefetch V chunks 0,1 into the two (now free) B buffers
    issueV(0, 0); CPCOMMIT();
    issueV(1, 1); CPCOMMIT();

    // softmax: scale, max, exp, sum (overlaps V prefetch)
    #pragma unroll
    for (int c = 0; c < 4; c++)
        #pragma unroll
        for (int nt = 0; nt < 4; nt++)
            #pragma unroll
            for (int p = 0; p < 4; p++) acc[c][nt][p] *= (1.f/64.f);

    const int r0 = wm*16 + g, r1 = r0 + 8;

    float mx0 = -1e30f, mx1 = -1e30f;
    #pragma unroll
    for (int c = 0; c < 4; c++)
        #pragma unroll
        for (int nt = 0; nt < 4; nt++){
            mx0 = fmaxf(mx0, fmaxf(acc[c][nt][0], acc[c][nt][1]));
            mx1 = fmaxf(mx1, fmaxf(acc[c][nt][2], acc[c][nt][3]));
        }
    #pragma unroll
    for (int o = 1; o <= 2; o <<= 1){
        mx0 = fmaxf(mx0, __shfl_xor_sync(~0u, mx0, o));
        mx1 = fmaxf(mx1, __shfl_xor_sync(~0u, mx1, o));
    }
    if (t == 0){ red[r0*4 + wn] = mx0; red[r1*4 + wn] = mx1; }
    __syncthreads();
    float rm0 = fmaxf(fmaxf(red[r0*4+0], red[r0*4+1]), fmaxf(red[r0*4+2], red[r0*4+3]));
    float rm1 = fmaxf(fmaxf(red[r1*4+0], red[r1*4+1]), fmaxf(red[r1*4+2], red[r1*4+3]));
    __syncthreads();

    float s0 = 0.f, s1 = 0.f;
    #pragma unroll
    for (int c = 0; c < 4; c++)
        #pragma unroll
        for (int nt = 0; nt < 4; nt++){
            acc[c][nt][0] = __expf(acc[c][nt][0] - rm0);
            acc[c][nt][1] = __expf(acc[c][nt][1] - rm0);
            acc[c][nt][2] = __expf(acc[c][nt][2] - rm1);
            acc[c][nt][3] = __expf(acc[c][nt][3] - rm1);
            s0 += acc[c][nt][0] + acc[c][nt][1];
            s1 += acc[c][nt][2] + acc[c][nt][3];
        }
    #pragma unroll
    for (int o = 1; o <= 2; o <<= 1){
        s0 += __shfl_xor_sync(~0u, s0, o);
        s1 += __shfl_xor_sync(~0u, s1, o);
    }
    if (t == 0){ red[r0*4 + wn] = s0; red[r1*4 + wn] = s1; }
    __syncthreads();
    float inv0 = 1.f / (red[r0*4+0] + red[r0*4+1] + red[r0*4+2] + red[r0*4+3]);
    float inv1 = 1.f / (red[r1*4+0] + red[r1*4+1] + red[r1*4+2] + red[r1*4+3]);

    // AV: per 128-col chunk stage tf32(series) in smem, mma against V chunk
    float yacc[2][4];
    #pragma unroll
    for (int nt = 0; nt < 2; nt++)
        #pragma unroll
        for (int p = 0; p < 4; p++) yacc[nt][p] = 0.f;

    float* Srow0 = dsm + (A_BYTES + 2*B_BYTES)/4;
    float* p0 = Sb + (long)r0*512;
    float* p1 = Sb + (long)r1*512;

    #pragma unroll
    for (int c = 0; c < 4; c++){
        #pragma unroll
        for (int nt = 0; nt < 4; nt++){
            int colc = wn*32 + nt*8 + 2*t;
            float n00 = acc[c][nt][0]*inv0, n01 = acc[c][nt][1]*inv0;
            float n10 = acc[c][nt][2]*inv1, n11 = acc[c][nt][3]*inv1;
            Srow0[r0*SST + colc]   = tf32r(n00);
            Srow0[r0*SST + colc+1] = tf32r(n01);
            Srow0[r1*SST + colc]   = tf32r(n10);
            Srow0[r1*SST + colc+1] = tf32r(n11);
            *(float2*)&p0[c*128 + colc] = make_float2(n00, n01);
            *(float2*)&p1[c*128 + colc] = make_float2(n10, n11);
        }
        if (c < 3) { CPWAIT(1); } else { CPWAIT(0); }
        __syncthreads();

        const unsigned vb = sbB + (unsigned)(c & 1) * B_BYTES;
        #pragma unroll
        for (int kg = 0; kg < 8; kg++){
            uint4 a0 = ldmx4(sF + (unsigned)(kg*16 + 0)*4);
            uint4 a1 = ldmx4(sF + (unsigned)(kg*16 + 8)*4);
            #pragma unroll
            for (int nt = 0; nt < 2; nt++){
                uint4 bv = ldmx4(vb + vF + (unsigned)(nt*8*VST + kg*16)*4);
                mma8(yacc[nt], a0.x, a0.y, a0.z, a0.w, bv.x, bv.y);
                mma8(yacc[nt], a1.x, a1.y, a1.z, a1.w, bv.z, bv.w);
            }
        }
        __syncthreads();
        if (c + 2 < 4){ issueV(c + 2, c & 1); }
        CPCOMMIT();
    }

    // write y tile
    #pragma unroll
    for (int nt = 0; nt < 2; nt++){
        int col = wn*16 + nt*8 + 2*t;
        int rowA = m0 + r0, rowB = m0 + r1;
        *(float2*)&Yb[(long)rowA*512 + col] = make_float2(yacc[nt][0], yacc[nt][1]);
        *(float2*)&Yb[(long)rowB*512 + col] = make_float2(yacc[nt][2], yacc[nt][3]);
    }
}

// ---------------------------------------------------------------------------
// prior + sigma_full
// ---------------------------------------------------------------------------
__global__ void prior_kernel(float* __restrict__ prior, float* __restrict__ sfull)
{
    long row = blockIdx.x;
    int n = (int)(row % TT);
    float s = g_sigma[row];
    float inv2 = -1.f / (2.f * s * s);
    float coef = 0.3989422804014327f / s;
    int tid = threadIdx.x;
    int m0 = tid * 4;
    float d0 = (float)(n - (m0 + 0));
    float d1 = (float)(n - (m0 + 1));
    float d2 = (float)(n - (m0 + 2));
    float d3 = (float)(n - (m0 + 3));
    float4 pv;
    pv.x = __expf(d0*d0*inv2) * coef;
    pv.y = __expf(d1*d1*inv2) * coef;
    pv.z = __expf(d2*d2*inv2) * coef;
    pv.w = __expf(d3*d3*inv2) * coef;
    ((float4*)(prior + row * TT))[tid] = pv;
    ((float4*)(sfull + row * TT))[tid] = make_float4(s, s, s, s);
}

// ---------------------------------------------------------------------------
// stylization
// ---------------------------------------------------------------------------
__global__ void style_kernel(const float* __restrict__ emb,
                             const float* __restrict__ embW,
                             const float* __restrict__ embB)
{
    int bb = blockIdx.y, tid = threadIdx.x;
    __shared__ float se[TEDIM];
    for (int i = tid; i < TEDIM; i += 256) {
        float e = emb[(size_t)bb * TEDIM + i];
        se[i] = siluf(e);
    }
    __syncthreads();
    int j = blockIdx.x * 256 + tid;
    float acc = 0.f;
    for (int k = 0; k < TEDIM; k++)
        acc += se[k] * embW[(size_t)k * (2*DDIM) + j];
    g_style[bb * (2*DDIM) + j] = acc + embB[j];
}

// ---------------------------------------------------------------------------
// LN2 + scale/shift + silu (hs stored tf32-rounded)
// ---------------------------------------------------------------------------
__global__ void ln2_style_kernel(const float* __restrict__ g,
                                 const float* __restrict__ b)
{
    int row = blockIdx.x;
    int tid = threadIdx.x;
    int warp = tid >> 5, lane = tid & 31;
    int bb = row / TT;
    const float* yr = g_y + (size_t)row * DDIM;
    float x0 = yr[tid], x1 = yr[tid + 256];
    float s = x0 + x1, sq = x0*x0 + x1*x1;
    #pragma unroll
    for (int o = 16; o > 0; o >>= 1) {
        s  += __shfl_xor_sync(~0u, s,  o);
        sq += __shfl_xor_sync(~0u, sq, o);
    }
    __shared__ float sm[8], sm2[8];
    if (lane == 0) { sm[warp] = s; sm2[warp] = sq; }
    __syncthreads();
    float tot = 0.f, tot2 = 0.f;
    #pragma unroll
    for (int i = 0; i < 8; i++) { tot += sm[i]; tot2 += sm2[i]; }
    float mean = tot * (1.f / DDIM);
    float var  = tot2 * (1.f / DDIM) - mean * mean;
    float rstd = rsqrtf(var + 1e-5f);
    float n0 = (x0 - mean) * rstd * g[tid]       + b[tid];
    float n1 = (x1 - mean) * rstd * g[tid + 256] + b[tid + 256];
    const float* st = g_style + bb * (2*DDIM);
    float h0 = n0 * (1.f + st[tid])       + st[512 + tid];
    float h1 = n1 * (1.f + st[tid + 256]) + st[512 + tid + 256];
    g_hs[(size_t)row*DDIM + tid]       = tf32r(siluf(h0));
    g_hs[(size_t)row*DDIM + tid + 256] = tf32r(siluf(h1));
}

// ---------------------------------------------------------------------------
extern "C" void kernel_launch(void* const* d_in, const int* in_sizes, int n_in,
                              void* d_out, int out_size)
{
    const float* x    = (const float*)d_in[0];
    const float* emb  = (const float*)d_in[1];
    const float* Wq   = (const float*)d_in[2];
    const float* Wk   = (const float*)d_in[3];
    const float* Wv   = (const float*)d_in[4];
    const float* Wsig = (const float*)d_in[5];
    const float* ln1g = (const float*)d_in[6];
    const float* ln1b = (const float*)d_in[7];
    const float* embW = (const float*)d_in[8];
    const float* embB = (const float*)d_in[9];
    const float* ln2g = (const float*)d_in[10];
    const float* ln2b = (const float*)d_in[11];
    const float* outW = (const float*)d_in[12];
    const float* outB = (const float*)d_in[13];

    float* out    = (float*)d_out;
    float* outY   = out;
    float* outS   = out + YN;
    float* outP   = outS + SN;
    float* outSig = outP + SN;

    float *pxn, *pq, *pk, *pv, *py, *phs, *pwr;
    cudaGetSymbolAddress((void**)&pxn, g_xn);
    cudaGetSymbolAddress((void**)&pq,  g_q);
    cudaGetSymbolAddress((void**)&pk,  g_k);
    cudaGetSymbolAddress((void**)&pv,  g_v);
    cudaGetSymbolAddress((void**)&py,  g_y);
    cudaGetSymbolAddress((void**)&phs, g_hs);
    cudaGetSymbolAddress((void**)&pwr, g_wr);

    const int SMG = 3*2*128*36*4;                            // 110592
    const int SMF = 8704 + 2*34816 + 32*132*4 + 512;         // 95744

    cudaFuncSetAttribute(tf32_gemm2<true >, cudaFuncAttributeMaxDynamicSharedMemorySize, SMG);
    cudaFuncSetAttribute(tf32_gemm2<false>, cudaFuncAttributeMaxDynamicSharedMemorySize, SMG);
    cudaFuncSetAttribute(fused_attn_kernel, cudaFuncAttributeMaxDynamicSharedMemorySize, SMF);

    // 0) pre-round weights to tf32 (g_wr[0:3*WSZ] = merged [1536,512] QKV)
    round_w_kernel<<<WSZ/256, 256>>>(Wq, Wk, Wv, outW);

    // 1) LN1 + sigma
    ln1_sigma_kernel<<<MROWS, 256>>>(x, ln1g, ln1b, Wsig);

    // 2) merged QKV projection (one launch, per-block routing)
    tf32_gemm2<true><<<dim3(12, MROWS/128), 256, SMG>>>(
        pxn, pwr, pq, pk, pv, nullptr, nullptr);

    // 3) fused scores + softmax + AV -> series (d_out) + y
    fused_attn_kernel<<<dim3(TT/32, BQ*HH), 256, SMF>>>(pq, pk, pv, outS, py);

    // 4) prior + sigma_full
    prior_kernel<<<BQ*HH*TT, 128>>>(outP, outSig);

    // 5) stylization embedding
    style_kernel<<<dim3(4, BQ), 256>>>(emb, embW, embB);

    // 6) LN2 + style + silu
    ln2_style_kernel<<<MROWS, 256>>>(ln2g, ln2b);

    // 7) y_out = x + silu_h @ out_W^T + out_b
    tf32_gemm2<false><<<dim3(4, MROWS/128), 256, SMG>>>(
        phs, pwr + 3*WSZ, outY, nullptr, nullptr, outB, x);
}

// round 7
// speedup vs baseline: 1.1052x; 1.1052x over previous
#include <cuda_runtime.h>

// Problem constants
#define BQ   32
#define TT   512
#define DDIM 512
#define HH   8
#define HD   64
#define TEDIM 2048
#define MROWS (BQ*TT)            // 16384
#define YN ((size_t)BQ*TT*DDIM)  // 8388608
#define SN ((size_t)BQ*HH*TT*TT) // 67108864
#define WSZ (DDIM*DDIM)          // 262144

// Scratch (device globals — no allocation allowed)
__device__ float g_xn[BQ*TT*DDIM];
__device__ float g_q [BQ*TT*DDIM];
__device__ float g_k [BQ*TT*DDIM];
__device__ float g_v [BQ*TT*DDIM];   // stored TRANSPOSED: [b][h*64+d][t]
__device__ float g_y [BQ*TT*DDIM];
__device__ float g_hs[BQ*TT*DDIM];
__device__ float g_sigma[BQ*HH*TT];
__device__ float g_style[BQ*2*DDIM];
__device__ float g_wr[4*WSZ];        // tf32-rounded [Wq;Wk;Wv] (1536x512) + outW

__device__ __forceinline__ float siluf(float z){ return z / (1.f + expf(-z)); }

__device__ __forceinline__ float tf32r(float f){
    unsigned u; asm("cvt.rna.tf32.f32 %0, %1;" : "=r"(u) : "f"(f));
    return __uint_as_float(u);
}

__device__ __forceinline__ void mma8(float* c,
    unsigned a0, unsigned a1, unsigned a2, unsigned a3,
    unsigned b0, unsigned b1)
{
    asm volatile(
        "mma.sync.aligned.m16n8k8.row.col.f32.tf32.tf32.f32 "
        "{%0,%1,%2,%3}, {%4,%5,%6,%7}, {%8,%9}, {%0,%1,%2,%3};"
        : "+f"(c[0]), "+f"(c[1]), "+f"(c[2]), "+f"(c[3])
        : "r"(a0), "r"(a1), "r"(a2), "r"(a3), "r"(b0), "r"(b1));
}

__device__ __forceinline__ void cp16(unsigned dst, const void* src){
    asm volatile("cp.async.cg.shared.global [%0], [%1], 16;" :: "r"(dst), "l"(src));
}
#define CPCOMMIT() asm volatile("cp.async.commit_group;" ::: "memory")
#define CPWAIT(n)  asm volatile("cp.async.wait_group %0;" :: "n"(n) : "memory")

__device__ __forceinline__ uint4 ldmx4(unsigned a){
    uint4 r;
    asm volatile("ldmatrix.sync.aligned.m8n8.x4.shared.b16 {%0,%1,%2,%3}, [%4];"
        : "=r"(r.x), "=r"(r.y), "=r"(r.z), "=r"(r.w) : "r"(a));
    return r;
}

// ---------------------------------------------------------------------------
// LN1 + sigma, with round_w blocks packed into the same launch.
// blocks [0,16384): LN1 rows.  blocks [16384,17408): weight pre-round.
// ---------------------------------------------------------------------------
__global__ void ln1_sigma_roundw_kernel(const float* __restrict__ x,
                                        const float* __restrict__ g,
                                        const float* __restrict__ b,
                                        const float* __restrict__ Wsig,
                                        const float* __restrict__ w0,
                                        const float* __restrict__ w1,
                                        const float* __restrict__ w2,
                                        const float* __restrict__ w3)
{
    int tid = threadIdx.x;
    if (blockIdx.x >= MROWS){
        int i = (blockIdx.x - MROWS) * 256 + tid;
        g_wr[i]         = tf32r(w0[i]);
        g_wr[i +   WSZ] = tf32r(w1[i]);
        g_wr[i + 2*WSZ] = tf32r(w2[i]);
        g_wr[i + 3*WSZ] = tf32r(w3[i]);
        return;
    }
    int row = blockIdx.x;
    int warp = tid >> 5, lane = tid & 31;
    const float* xr = x + (size_t)row * DDIM;
    float x0 = xr[tid], x1 = xr[tid + 256];
    float s = x0 + x1, sq = x0*x0 + x1*x1;
    #pragma unroll
    for (int o = 16; o > 0; o >>= 1) {
        s  += __shfl_xor_sync(~0u, s,  o);
        sq += __shfl_xor_sync(~0u, sq, o);
    }
    __shared__ float sm[8], sm2[8];
    if (lane == 0) { sm[warp] = s; sm2[warp] = sq; }
    __syncthreads();
    float tot = 0.f, tot2 = 0.f;
    #pragma unroll
    for (int i = 0; i < 8; i++) { tot += sm[i]; tot2 += sm2[i]; }
    float mean = tot * (1.f / DDIM);
    float var  = tot2 * (1.f / DDIM) - mean * mean;
    float rstd = rsqrtf(var + 1e-5f);
    g_xn[(size_t)row*DDIM + tid]       = tf32r((x0 - mean) * rstd * g[tid]       + b[tid]);
    g_xn[(size_t)row*DDIM + tid + 256] = tf32r((x1 - mean) * rstd * g[tid + 256] + b[tid + 256]);

    float acc[HH];
    #pragma unroll
    for (int h = 0; h < HH; h++)
        acc[h] = x0 * Wsig[tid*HH + h] + x1 * Wsig[(tid+256)*HH + h];
    #pragma unroll
    for (int h = 0; h < HH; h++)
        #pragma unroll
        for (int o = 16; o > 0; o >>= 1)
            acc[h] += __shfl_xor_sync(~0u, acc[h], o);
    __shared__ float red[8][HH];
    if (lane == 0)
        #pragma unroll
        for (int h = 0; h < HH; h++) red[warp][h] = acc[h];
    __syncthreads();
    if (tid < HH) {
        float z = 0.f;
        #pragma unroll
        for (int w = 0; w < 8; w++) z += red[w][tid];
        float sg  = 1.f / (1.f + expf(-5.f * z)) + 1e-5f;
        float sig = exp2f(sg * 1.5849625007211562f) - 1.f;   // 3^sg - 1
        int bb = row / TT, t = row % TT;
        g_sigma[(bb*HH + tid)*TT + t] = sig;
    }
}

// ---------------------------------------------------------------------------
// tf32 NT GEMM v2 (BK=32, 3-stage cp.async, merged-QKV routing / outproj).
// ---------------------------------------------------------------------------
template<bool QKV>
__global__ void __launch_bounds__(256,2)
tf32_gemm2(const float* __restrict__ A, const float* __restrict__ Bw,
           float* __restrict__ Cq, float* __restrict__ Ck, float* __restrict__ Cv,
           const float* __restrict__ bias, const float* __restrict__ res)
{
    constexpr int ST  = 36;                // 32 + 4 pad (floats)
    constexpr int STG = 128*ST*4;          // per-operand stage bytes

    extern __shared__ float dsm[];
    const unsigned sb = (unsigned)__cvta_generic_to_shared(dsm);
    const unsigned aS = sb;
    const unsigned bS = sb + 3*STG;

    const int tid  = threadIdx.x;
    const int lane = tid & 31;
    const int wid  = tid >> 5;
    const int wm   = wid & 1;
    const int wn   = wid >> 1;
    const int g    = lane >> 2;
    const int t    = lane & 3;

    const int m0 = blockIdx.y * 128;
    const int n0 = blockIdx.x * 128;

    const int rl = tid >> 3;               // 0..31
    const int qc = tid & 7;                // 16B chunk in BK32

    const float* Ag = A  + (long)(m0 + rl) * 512 + qc*4;
    const float* Bg = Bw + (long)(n0 + rl) * 512 + qc*4;
    const unsigned dA = (unsigned)(rl*ST + qc*4) * 4;

    auto issue = [&](int st, int k0){
        unsigned ab = aS + st*STG, bb = bS + st*STG;
        #pragma unroll
        for (int e = 0; e < 4; e++){
            cp16(ab + dA + e*32*ST*4, Ag + (long)e*32*512 + k0);
            cp16(bb + dA + e*32*ST*4, Bg + (long)e*32*512 + k0);
        }
    };

    const int arow = (lane & 7) + ((lane >> 3) & 1) * 8;
    const int acol = (lane >> 4) * 4;
    const unsigned aFB = (unsigned)((wm*64 + arow)*ST + acol) * 4;
    const unsigned bFB = (unsigned)((wn*32 + (lane & 7))*ST + (lane >> 3)*4) * 4;

    float acc[4][4][4];
    #pragma unroll
    for (int i = 0; i < 4; i++)
        #pragma unroll
        for (int j = 0; j < 4; j++)
            #pragma unroll
            for (int p = 0; p < 4; p++) acc[i][j][p] = 0.f;

    issue(0, 0);  CPCOMMIT();
    issue(1, 32); CPCOMMIT();

    int buf = 0;
    for (int k0 = 0; k0 < 512; k0 += 32) {
        CPWAIT(1);
        __syncthreads();
        if (k0 + 64 < 512) {
            int nb = buf + 2; if (nb >= 3) nb -= 3;
            issue(nb, k0 + 64);
        }
        CPCOMMIT();

        const unsigned ab = aS + buf*STG;
        const unsigned bb = bS + buf*STG;

        uint4 bfr[4][2];
        #pragma unroll
        for (int nt = 0; nt < 4; nt++)
            #pragma unroll
            for (int kg = 0; kg < 2; kg++)
                bfr[nt][kg] = ldmx4(bb + bFB + (unsigned)(nt*8*ST + kg*16)*4);

        #pragma unroll
        for (int ks = 0; ks < 4; ks++) {
            #pragma unroll
            for (int mt = 0; mt < 4; mt++) {
                uint4 a = ldmx4(ab + aFB + (unsigned)(mt*16*ST + ks*8)*4);
                #pragma unroll
                for (int nt = 0; nt < 4; nt++)
                    mma8(acc[mt][nt], a.x, a.y, a.z, a.w,
                         (ks & 1) ? bfr[nt][ks>>1].z : bfr[nt][ks>>1].x,
                         (ks & 1) ? bfr[nt][ks>>1].w : bfr[nt][ks>>1].y);
            }
        }
        buf++; if (buf == 3) buf = 0;
    }

    // Epilogue
    #pragma unroll
    for (int mt = 0; mt < 4; mt++){
        #pragma unroll
        for (int nt = 0; nt < 4; nt++){
            int row = m0 + wm*64 + mt*16 + g;
            int col = n0 + wn*32 + nt*8 + 2*t;
            float v0 = acc[mt][nt][0], v1 = acc[mt][nt][1];
            float v2 = acc[mt][nt][2], v3 = acc[mt][nt][3];
            if (QKV){
                v0 = tf32r(v0); v1 = tf32r(v1); v2 = tf32r(v2); v3 = tf32r(v3);
                if (n0 < 512){
                    *(float2*)&Cq[(long)row*512 + col]     = make_float2(v0, v1);
                    *(float2*)&Cq[(long)(row+8)*512 + col] = make_float2(v2, v3);
                } else if (n0 < 1024){
                    int c2 = col - 512;
                    *(float2*)&Ck[(long)row*512 + c2]     = make_float2(v0, v1);
                    *(float2*)&Ck[(long)(row+8)*512 + c2] = make_float2(v2, v3);
                } else {
                    int vc = col - 1024;
                    long base0 = (long)(row >> 9) * (512L*512) + (row & 511);
                    Cv[base0 + (long)vc*512]         = v0;
                    Cv[base0 + (long)(vc+1)*512]     = v1;
                    Cv[base0 + 8 + (long)vc*512]     = v2;
                    Cv[base0 + 8 + (long)(vc+1)*512] = v3;
                }
            } else {
                v0 += bias[col];   v1 += bias[col+1];
                v2 += bias[col];   v3 += bias[col+1];
                v0 += res[(long)row*512 + col];
                v1 += res[(long)row*512 + col+1];
                v2 += res[(long)(row+8)*512 + col];
                v3 += res[(long)(row+8)*512 + col+1];
                *(float2*)&Cq[(long)row*512 + col]     = make_float2(v0, v1);
                *(float2*)&Cq[(long)(row+8)*512 + col] = make_float2(v2, v3);
            }
        }
    }
}

// ---------------------------------------------------------------------------
// MEGA kernel: attention tiles + prior fill + style GEMV in ONE launch.
//   blocks [0,8192) even: attention tile idx = bx>>1 (bh = idx>>4, m0=(idx&15)*32)
//   blocks [0,8192) odd : prior slab idx = bx>>1 (32 rows each)
//   blocks [8192,8320)  : style (sb = bx-8192; bb = sb>>2, part = sb&3)
// ---------------------------------------------------------------------------
__global__ void __launch_bounds__(256,2)
mega_attn_kernel(const float* __restrict__ Q, const float* __restrict__ Kt,
                 const float* __restrict__ Vt,
                 float* __restrict__ S, float* __restrict__ Y,
                 float* __restrict__ prior, float* __restrict__ sfull,
                 const float* __restrict__ emb,
                 const float* __restrict__ embW,
                 const float* __restrict__ embB)
{
    extern __shared__ float dsm[];
    const int tid  = threadIdx.x;
    const unsigned bx = blockIdx.x;

    // ---------------- style blocks ----------------
    if (bx >= 8192){
        int sb = bx - 8192;
        int bb = sb >> 2, part = sb & 3;
        float* se = dsm;
        for (int i = tid; i < TEDIM; i += 256){
            float e = emb[(size_t)bb * TEDIM + i];
            se[i] = siluf(e);
        }
        __syncthreads();
        int j = part*256 + tid;
        float acc = 0.f;
        for (int k = 0; k < TEDIM; k++)
            acc += se[k] * embW[(size_t)k * (2*DDIM) + j];
        g_style[bb * (2*DDIM) + j] = acc + embB[j];
        return;
    }

    // ---------------- prior blocks ----------------
    if (bx & 1){
        long base = (long)(bx >> 1) * 32;         // first row of 32-row slab
        int w = tid >> 5, l = tid & 31;
        #pragma unroll
        for (int i = 0; i < 4; i++){
            long row = base + w*4 + i;            // (b*H+h)*T + n
            int n = (int)(row & 511);
            float s = g_sigma[row];
            float inv2 = -1.f / (2.f * s * s);
            float coef = 0.3989422804014327f / s;
            float4 sv = make_float4(s, s, s, s);
            float4* pp = (float4*)(prior + row * TT);
            float4* sp = (float4*)(sfull + row * TT);
            #pragma unroll
            for (int j = 0; j < 4; j++){
                int c4 = l + j*32;                // float4 index 0..127
                int m = c4 * 4;
                float d0 = (float)(n - m);
                float d1 = (float)(n - (m+1));
                float d2 = (float)(n - (m+2));
                float d3 = (float)(n - (m+3));
                float4 pv;
                pv.x = __expf(d0*d0*inv2) * coef;
                pv.y = __expf(d1*d1*inv2) * coef;
                pv.z = __expf(d2*d2*inv2) * coef;
                pv.w = __expf(d3*d3*inv2) * coef;
                pp[c4] = pv;
                sp[c4] = sv;
            }
        }
        return;
    }

    // ---------------- attention blocks ----------------
    const int idx = bx >> 1;
    const int bh = idx >> 4;          // b*8+h
    const int m0 = (idx & 15) * 32;

    constexpr int AST = 68;
    constexpr int BST = 68;
    constexpr int VST = 132;
    constexpr int SST = 132;
    const unsigned A_BYTES = 32*AST*4;            // 8704
    const unsigned B_BYTES = 128*BST*4;           // 34816

    const unsigned sb  = (unsigned)__cvta_generic_to_shared(dsm);
    const unsigned sbA = sb;
    const unsigned sbB = sb + A_BYTES;
    const unsigned sbS = sb + A_BYTES + 2*B_BYTES;       // series chunk 32x132
    float* red = dsm + (A_BYTES + 2*B_BYTES)/4 + 32*SST; // [32][4]

    const int lane = tid & 31;
    const int wid  = tid >> 5;
    const int wm   = wid & 1;
    const int wn   = wid >> 1;        // 0..3
    const int g    = lane >> 2;
    const int t    = lane & 3;

    const int b  = bh >> 3, h = bh & 7;

    const float* Qb = Q + ((long)b*512 + m0)*512 + h*64;
    const float* Kb = Kt + ((long)b*512)*512 + h*64;
    const float* Vb = Vt + (long)b*(512L*512) + (long)h*64*512; // [64 d][512 t]
    float* Sb = S + ((long)bh*512 + m0)*512;
    float* Yb = Y + ((long)b*512)*512 + h*64;

    const int arow = (lane & 7) + ((lane >> 3) & 1) * 8;
    const int acol = (lane >> 4) * 4;
    const unsigned aF  = sbA + (unsigned)((wm*16 + arow)*AST + acol) * 4;
    const unsigned bF  = (unsigned)((wn*32 + (lane & 7))*BST + (lane >> 3)*4) * 4;
    const unsigned sF  = sbS + (unsigned)((wm*16 + arow)*SST + acol) * 4;
    const unsigned vF  = (unsigned)((wn*16 + (lane & 7))*VST + (lane >> 3)*4) * 4;

    auto issueB = [&](int chunk, int bufb){
        unsigned dst = sbB + (unsigned)bufb * B_BYTES;
        const float* src = Kb + (long)(chunk*128)*512;
        #pragma unroll
        for (int e = 0; e < 8; e++){
            int idx2 = tid + 256*e;
            int r = idx2 >> 4, c4 = idx2 & 15;
            cp16(dst + (unsigned)(r*BST + c4*4)*4, src + (long)r*512 + c4*4);
        }
    };
    auto issueV = [&](int chunk, int bufb){
        unsigned dst = sbB + (unsigned)bufb * B_BYTES;
        #pragma unroll
        for (int e = 0; e < 8; e++){
            int idx2 = tid + 256*e;       // 0..2047
            int r  = idx2 >> 5;           // 0..63  (d-row)
            int qc = idx2 & 31;           // 0..31  (16B chunk of 128 t-cols)
            cp16(dst + (unsigned)(r*VST + qc*4)*4,
                 Vb + (long)r*512 + chunk*128 + qc*4);
        }
    };

    // group 0: Q tile + K chunk 0
    {
        #pragma unroll
        for (int e = 0; e < 2; e++){
            int idx2 = tid + 256*e;
            int r = idx2 >> 4, c4 = idx2 & 15;
            cp16(sbA + (unsigned)(r*AST + c4*4)*4, Qb + (long)r*512 + c4*4);
        }
        issueB(0, 0);
        CPCOMMIT();
    }

    float acc[4][4][4];
    #pragma unroll
    for (int c = 0; c < 4; c++)
        #pragma unroll
        for (int nt = 0; nt < 4; nt++)
            #pragma unroll
            for (int p = 0; p < 4; p++) acc[c][nt][p] = 0.f;

    for (int c = 0; c < 4; c++){
        CPWAIT(0);
        __syncthreads();
        if (c + 1 < 4) issueB(c + 1, (c + 1) & 1);
        CPCOMMIT();

        const unsigned bb2 = sbB + (unsigned)(c & 1) * B_BYTES;
        #pragma unroll
        for (int kg = 0; kg < 4; kg++){
            uint4 a0 = ldmx4(aF + (unsigned)(kg*16 + 0)*4);
            uint4 a1 = ldmx4(aF + (unsigned)(kg*16 + 8)*4);
            #pragma unroll
            for (int nt = 0; nt < 4; nt++){
                uint4 bv = ldmx4(bb2 + bF + (unsigned)(nt*8*BST + kg*16)*4);
                mma8(acc[c][nt], a0.x, a0.y, a0.z, a0.w, bv.x, bv.y);
                mma8(acc[c][nt], a1.x, a1.y, a1.z, a1.w, bv.z, bv.w);
            }
        }
        __syncthreads();
    }

    // prefetch V chunks 0,1 into the two (now free) B buffers
    issueV(0, 0); CPCOMMIT();
    issueV(1, 1); CPCOMMIT();

    // softmax: scale, max, exp, sum (overlaps V prefetch)
    #pragma unroll
    for (int c = 0; c < 4; c++)
        #pragma unroll
        for (int nt = 0; nt < 4; nt++)
            #pragma unroll
            for (int p = 0; p < 4; p++) acc[c][nt][p] *= (1.f/64.f);

    const int r0 = wm*16 + g, r1 = r0 + 8;

    float mx0 = -1e30f, mx1 = -1e30f;
    #pragma unroll
    for (int c = 0; c < 4; c++)
        #pragma unroll
        for (int nt = 0; nt < 4; nt++){
            mx0 = fmaxf(mx0, fmaxf(acc[c][nt][0], acc[c][nt][1]));
            mx1 = fmaxf(mx1, fmaxf(acc[c][nt][2], acc[c][nt][3]));
        }
    #pragma unroll
    for (int o = 1; o <= 2; o <<= 1){
        mx0 = fmaxf(mx0, __shfl_xor_sync(~0u, mx0, o));
        mx1 = fmaxf(mx1, __shfl_xor_sync(~0u, mx1, o));
    }
    if (t == 0){ red[r0*4 + wn] = mx0; red[r1*4 + wn] = mx1; }
    __syncthreads();
    float rm0 = fmaxf(fmaxf(red[r0*4+0], red[r0*4+1]), fmaxf(red[r0*4+2], red[r0*4+3]));
    float rm1 = fmaxf(fmaxf(red[r1*4+0], red[r1*4+1]), fmaxf(red[r1*4+2], red[r1*4+3]));
    __syncthreads();

    float s0 = 0.f, s1 = 0.f;
    #pragma unroll
    for (int c = 0; c < 4; c++)
        #pragma unroll
        for (int nt = 0; nt < 4; nt++){
            acc[c][nt][0] = __expf(acc[c][nt][0] - rm0);
            acc[c][nt][1] = __expf(acc[c][nt][1] - rm0);
            acc[c][nt][2] = __expf(acc[c][nt][2] - rm1);
            acc[c][nt][3] = __expf(acc[c][nt][3] - rm1);
            s0 += acc[c][nt][0] + acc[c][nt][1];
            s1 += acc[c][nt][2] + acc[c][nt][3];
        }
    #pragma unroll
    for (int o = 1; o <= 2; o <<= 1){
        s0 += __shfl_xor_sync(~0u, s0, o);
        s1 += __shfl_xor_sync(~0u, s1, o);
    }
    if (t == 0){ red[r0*4 + wn] = s0; red[r1*4 + wn] = s1; }
    __syncthreads();
    float inv0 = 1.f / (red[r0*4+0] + red[r0*4+1] + red[r0*4+2] + red[r0*4+3]);
    float inv1 = 1.f / (red[r1*4+0] + red[r1*4+1] + red[r1*4+2] + red[r1*4+3]);

    // AV: per 128-col chunk stage tf32(series) in smem, mma against V chunk
    float yacc[2][4];
    #pragma unroll
    for (int nt = 0; nt < 2; nt++)
        #pragma unroll
        for (int p = 0; p < 4; p++) yacc[nt][p] = 0.f;

    float* Srow0 = dsm + (A_BYTES + 2*B_BYTES)/4;
    float* p0 = Sb + (long)r0*512;
    float* p1 = Sb + (long)r1*512;

    #pragma unroll
    for (int c = 0; c < 4; c++){
        #pragma unroll
        for (int nt = 0; nt < 4; nt++){
            int colc = wn*32 + nt*8 + 2*t;
            float n00 = acc[c][nt][0]*inv0, n01 = acc[c][nt][1]*inv0;
            float n10 = acc[c][nt][2]*inv1, n11 = acc[c][nt][3]*inv1;
            Srow0[r0*SST + colc]   = tf32r(n00);
            Srow0[r0*SST + colc+1] = tf32r(n01);
            Srow0[r1*SST + colc]   = tf32r(n10);
            Srow0[r1*SST + colc+1] = tf32r(n11);
            *(float2*)&p0[c*128 + colc] = make_float2(n00, n01);
            *(float2*)&p1[c*128 + colc] = make_float2(n10, n11);
        }
        if (c < 3) { CPWAIT(1); } else { CPWAIT(0); }
        __syncthreads();

        const unsigned vb = sbB + (unsigned)(c & 1) * B_BYTES;
        #pragma unroll
        for (int kg = 0; kg < 8; kg++){
            uint4 a0 = ldmx4(sF + (unsigned)(kg*16 + 0)*4);
            uint4 a1 = ldmx4(sF + (unsigned)(kg*16 + 8)*4);
            #pragma unroll
            for (int nt = 0; nt < 2; nt++){
                uint4 bv = ldmx4(vb + vF + (unsigned)(nt*8*VST + kg*16)*4);
                mma8(yacc[nt], a0.x, a0.y, a0.z, a0.w, bv.x, bv.y);
                mma8(yacc[nt], a1.x, a1.y, a1.z, a1.w, bv.z, bv.w);
            }
        }
        __syncthreads();
        if (c + 2 < 4){ issueV(c + 2, c & 1); }
        CPCOMMIT();
    }

    // write y tile
    #pragma unroll
    for (int nt = 0; nt < 2; nt++){
        int col = wn*16 + nt*8 + 2*t;
        int rowA = m0 + r0, rowB = m0 + r1;
        *(float2*)&Yb[(long)rowA*512 + col] = make_float2(yacc[nt][0], yacc[nt][1]);
        *(float2*)&Yb[(long)rowB*512 + col] = make_float2(yacc[nt][2], yacc[nt][3]);
    }
}

// ---------------------------------------------------------------------------
// LN2 + scale/shift + silu (hs stored tf32-rounded)
// ---------------------------------------------------------------------------
__global__ void ln2_style_kernel(const float* __restrict__ g,
                                 const float* __restrict__ b)
{
    int row = blockIdx.x;
    int tid = threadIdx.x;
    int warp = tid >> 5, lane = tid & 31;
    int bb = row / TT;
    const float* yr = g_y + (size_t)row * DDIM;
    float x0 = yr[tid], x1 = yr[tid + 256];
    float s = x0 + x1, sq = x0*x0 + x1*x1;
    #pragma unroll
    for (int o = 16; o > 0; o >>= 1) {
        s  += __shfl_xor_sync(~0u, s,  o);
        sq += __shfl_xor_sync(~0u, sq, o);
    }
    __shared__ float sm[8], sm2[8];
    if (lane == 0) { sm[warp] = s; sm2[warp] = sq; }
    __syncthreads();
    float tot = 0.f, tot2 = 0.f;
    #pragma unroll
    for (int i = 0; i < 8; i++) { tot += sm[i]; tot2 += sm2[i]; }
    float mean = tot * (1.f / DDIM);
    float var  = tot2 * (1.f / DDIM) - mean * mean;
    float rstd = rsqrtf(var + 1e-5f);
    float n0 = (x0 - mean) * rstd * g[tid]       + b[tid];
    float n1 = (x1 - mean) * rstd * g[tid + 256] + b[tid + 256];
    const float* st = g_style + bb * (2*DDIM);
    float h0 = n0 * (1.f + st[tid])       + st[512 + tid];
    float h1 = n1 * (1.f + st[tid + 256]) + st[512 + tid + 256];
    g_hs[(size_t)row*DDIM + tid]       = tf32r(siluf(h0));
    g_hs[(size_t)row*DDIM + tid + 256] = tf32r(siluf(h1));
}

// ---------------------------------------------------------------------------
extern "C" void kernel_launch(void* const* d_in, const int* in_sizes, int n_in,
                              void* d_out, int out_size)
{
    const float* x    = (const float*)d_in[0];
    const float* emb  = (const float*)d_in[1];
    const float* Wq   = (const float*)d_in[2];
    const float* Wk   = (const float*)d_in[3];
    const float* Wv   = (const float*)d_in[4];
    const float* Wsig = (const float*)d_in[5];
    const float* ln1g = (const float*)d_in[6];
    const float* ln1b = (const float*)d_in[7];
    const float* embW = (const float*)d_in[8];
    const float* embB = (const float*)d_in[9];
    const float* ln2g = (const float*)d_in[10];
    const float* ln2b = (const float*)d_in[11];
    const float* outW = (const float*)d_in[12];
    const float* outB = (const float*)d_in[13];

    float* out    = (float*)d_out;
    float* outY   = out;
    float* outS   = out + YN;
    float* outP   = outS + SN;
    float* outSig = outP + SN;

    float *pxn, *pq, *pk, *pv, *py, *phs, *pwr;
    cudaGetSymbolAddress((void**)&pxn, g_xn);
    cudaGetSymbolAddress((void**)&pq,  g_q);
    cudaGetSymbolAddress((void**)&pk,  g_k);
    cudaGetSymbolAddress((void**)&pv,  g_v);
    cudaGetSymbolAddress((void**)&py,  g_y);
    cudaGetSymbolAddress((void**)&phs, g_hs);
    cudaGetSymbolAddress((void**)&pwr, g_wr);

    const int SMG = 3*2*128*36*4;                            // 110592
    const int SMF = 8704 + 2*34816 + 32*132*4 + 512;         // 95744

    cudaFuncSetAttribute(tf32_gemm2<true >, cudaFuncAttributeMaxDynamicSharedMemorySize, SMG);
    cudaFuncSetAttribute(tf32_gemm2<false>, cudaFuncAttributeMaxDynamicSharedMemorySize, SMG);
    cudaFuncSetAttribute(mega_attn_kernel,  cudaFuncAttributeMaxDynamicSharedMemorySize, SMF);

    // 1) LN1 + sigma + weight pre-round (packed)
    ln1_sigma_roundw_kernel<<<MROWS + WSZ/256, 256>>>(
        x, ln1g, ln1b, Wsig, Wq, Wk, Wv, outW);

    // 2) merged QKV projection (one launch, per-block routing)
    tf32_gemm2<true><<<dim3(12, MROWS/128), 256, SMG>>>(
        pxn, pwr, pq, pk, pv, nullptr, nullptr);

    // 3) MEGA: attention (scores+softmax+AV) + prior + sigma_full + style
    mega_attn_kernel<<<8192 + 128, 256, SMF>>>(
        pq, pk, pv, outS, py, outP, outSig, emb, embW, embB);

    // 4) LN2 + style + silu
    ln2_style_kernel<<<MROWS, 256>>>(ln2g, ln2b);

    // 5) y_out = x + silu_h @ out_W^T + out_b
    tf32_gemm2<false><<<dim3(4, MROWS/128), 256, SMG>>>(
        phs, pwr + 3*WSZ, outY, nullptr, nullptr, outB, x);
}